// round 8
// baseline (speedup 1.0000x reference)
#include <cuda_runtime.h>

// ---------------------------------------------------------------------------
// ResonantComplexProjection
//   theta[b,n,i] = x[b,i] / (1+|W[n,i]|) + B[n,i]
//   idx = floor(theta * 4096/2pi) mod 4096   (LUT sin/cos, 4096 entries)
//   cos_sum[b,n] = sum_i cos_lut[idx];  sin_sum likewise
//   real = cos_sum @ Wr^T ; imag = sin_sum @ Wi^T
// Shapes: batch=256, in_f=512, n_neur=1024, out_f=512
// ---------------------------------------------------------------------------

#define LUT_HALF 4608                  // table covers k in [-4608, 4608)
#define LUT_N    (2 * LUT_HALF)        // 9216 entries (float2: sin, cos)
#define SMEM_MAIN (LUT_N * 8 + 16384)  // 72KB LUT + 16KB x tile = 90112 B (occ 2)

static __device__ float4 g_lut4[LUT_N / 2];    // 2 (sin,cos) entries per float4
static __device__ float4 g_rsbs[256 * 1024];   // [ipair][n] -> {rs0, rs1, bs0, bs1}
static __device__ float  g_A[2 * 262144];      // [p][b][k]: p0=cos, p1=sin
static __device__ float  g_part[8][262144];    // [ksplit][p*131072 + b*512 + o]

// ---------------------------------------------------------------------------
// Fused init: blocks [0,18) build the LUT; blocks [18,1042) build rs/bs.
// ---------------------------------------------------------------------------

__global__ void k_init(const float* __restrict__ W, const float* __restrict__ B) {
    const int bid = blockIdx.x;
    const int tid = threadIdx.x;
    if (bid < 18) {
        int t = bid * 256 + tid;                   // < 4608
        const float step = (float)(6.283185307179586476925287 / 4096.0);
        int k0 = 2 * t - LUT_HALF;
        int j0 = k0 & 4095;                        // floor-mod 4096 (matches Python %)
        int j1 = (k0 + 1) & 4095;
        float a0 = (float)j0 * step;
        float a1 = (float)j1 * step;
        float4 e;
        e.x = sinf(a0); e.y = cosf(a0);
        e.z = sinf(a1); e.w = cosf(a1);
        g_lut4[t] = e;
    } else {
        int e = (bid - 18) * 256 + tid;            // < 262144
        int n  = e & 1023;
        int ip = e >> 10;
        const float S = (float)(4096.0 / 6.283185307179586476925287);
        float2 w = ((const float2*)(W + n * 512))[ip];
        float2 b = ((const float2*)(B + n * 512))[ip];
        float4 v;
        v.x = S / (1.0f + fabsf(w.x));
        v.y = S / (1.0f + fabsf(w.y));
        v.z = S * b.x - 0.5f;                      // fold floor(v)=round(v-0.5) shift
        v.w = S * b.y - 0.5f;
        g_rsbs[e] = v;                             // e = ip*1024 + n
    }
}

// ---------------------------------------------------------------------------
// Packed f32x2 helpers
// ---------------------------------------------------------------------------

__device__ __forceinline__ unsigned long long fma2_(unsigned long long a,
                                                    unsigned long long b,
                                                    unsigned long long c) {
    unsigned long long d;
    asm("fma.rn.f32x2 %0, %1, %2, %3;" : "=l"(d) : "l"(a), "l"(b), "l"(c));
    return d;
}
__device__ __forceinline__ unsigned long long add2_(unsigned long long a,
                                                    unsigned long long b) {
    unsigned long long d;
    asm("add.rn.f32x2 %0, %1, %2;" : "=l"(d) : "l"(a), "l"(b));
    return d;
}
__device__ __forceinline__ unsigned long long lds64_(unsigned a) {
    unsigned long long v;
    asm("ld.shared.b64 %0, [%1];" : "=l"(v) : "r"(a));
    return v;
}

// ---------------------------------------------------------------------------
// k_main v2: 296 blocks (= 148 SMs x occ 2,每 SM exactly 2 via bid%148 map).
// Flat list of 1024 fine tiles (32 n x 8 batch x full 512 i); block bid takes
// tiles [floor(1024*bid/296), floor(1024*(bid+1)/296)) -> per-SM totals 6 or 7
// (1.2% imbalance vs 13% before). Full-i tiles -> direct g_A stores, no halves,
// no combine pass, no atomics.
// Inner loop per (pair, b): 1 LDG.128 (rs|bs packed) + LDS.64 x-broadcast +
// FMA2 + ADD2(magic) + 2 LDS.64 LUT gathers + 2 ADD2. Magic-number floor +
// extended LUT addressing identical to the proven version.
// ---------------------------------------------------------------------------

__global__ __launch_bounds__(256, 2) void k_main(const float* __restrict__ x) {
    extern __shared__ unsigned char smem[];
    float4* lut4 = (float4*)smem;
    unsigned long long* xs2 = (unsigned long long*)(smem + LUT_N * 8);  // [8 b][256 ipair]

    const int tid = threadIdx.x;
    const int bid = blockIdx.x;

#pragma unroll
    for (int t = 0; t < (LUT_N / 2) / 256; t++)        // stage 72KB LUT (18 iters)
        lut4[tid + t * 256] = g_lut4[tid + t * 256];

    const unsigned cbase =
        (unsigned)__cvta_generic_to_shared(smem) + (unsigned)(LUT_HALF * 8) - 0x5A000000u;
    const unsigned long long MAGIC2 = 0x4B4000004B400000ULL;

    const int lo = (128 * bid) / 37;          // = floor(1024*bid/296)
    const int hi = (128 * (bid + 1)) / 37;

    const int nl = tid & 31;                  // n within 32-wide tile
    const int bl = tid >> 5;                  // batch within 8-wide group (warp-uniform)

    int cur_bg = -1;
    for (int t = lo; t < hi; t++) {
        const int nt = t & 31;                // 32 n-tiles of 32
        const int bg = t >> 5;                // 32 batch-groups of 8

        if (bg != cur_bg) {                   // stage x[bg*8 .. +8][all 512 i] (16KB)
            __syncthreads();
            const unsigned long long* xg = (const unsigned long long*)x;
#pragma unroll
            for (int k = 0; k < 8; k++) {
                int e = tid + (k << 8);                       // < 2048
                xs2[e] = xg[((bg << 3) + (e >> 8)) * 256 + (e & 255)];
            }
            __syncthreads();
            cur_bg = bg;
        }

        const int n = (nt << 5) + nl;
        const ulonglong2* rb = (const ulonglong2*)g_rsbs + n;   // + ip*1024
        const unsigned long long* xp_ = xs2 + (bl << 8);

        unsigned long long accE = 0ULL, accO = 0ULL;
#pragma unroll 4
        for (int ip = 0; ip < 256; ip++) {
            ulonglong2 rv = __ldg(rb + ip * 1024);   // rv.x={rs0,rs1}, rv.y={bs0,bs1}
            unsigned long long xp = xp_[ip];          // uniform-addr broadcast LDS.64
            unsigned long long w  = add2_(fma2_(xp, rv.x, rv.y), MAGIC2);
            unsigned qlo, qhi;
            asm("mov.b64 {%0, %1}, %2;" : "=r"(qlo), "=r"(qhi) : "l"(w));
            accE = add2_(accE, lds64_(qlo * 8u + cbase));
            accO = add2_(accO, lds64_(qhi * 8u + cbase));
        }

        unsigned long long acc = add2_(accE, accO);   // {sin_sum, cos_sum}
        unsigned slo, shi;
        asm("mov.b64 {%0, %1}, %2;" : "=r"(slo), "=r"(shi) : "l"(acc));
        const int idx = ((bg << 3) + bl) * 1024 + n;  // [b][k=n]
        g_A[idx]          = __uint_as_float(shi);     // cos plane
        g_A[262144 + idx] = __uint_as_float(slo);     // sin plane
    }
}

// ---------------------------------------------------------------------------
// k_gemm4 (UNCHANGED — proven): split-K GEMM, 64x64 tile, double-buffered,
// one sync per BK-chunk, `#pragma unroll 1` outer loop.
// grid (4,8,16) = 512 blocks: plane p (2) x K-split of 128 (8).
// ---------------------------------------------------------------------------

#define BK 16
#define LDP 68    // smem row stride in floats (float4-aligned)

__global__ __launch_bounds__(256, 3) void k_gemm4(const float* __restrict__ Wr,
                                                  const float* __restrict__ Wi) {
    __shared__ float As[2][BK][LDP];
    __shared__ float Bs[2][BK][LDP];

    const int tid = threadIdx.x;
    const int b0 = blockIdx.x << 6;
    const int o0 = blockIdx.y << 6;
    const int z  = blockIdx.z;
    const int pp = z >> 3;               // 0=real(cos), 1=imag(sin)
    const int s  = z & 7;                // K-split (128 each)

    const float* Ap = g_A + pp * 262144;
    const float* Wp = pp ? Wi : Wr;

    const int tx = tid & 15, ty = tid >> 4;
    const int lk = tid & 15;             // k within chunk
    const int lm = tid >> 4;             // base row 0..15 (4 strided rows)
    const int kbase = s << 7;

    float ar[4], br[4];
#pragma unroll
    for (int t = 0; t < 4; t++) {
        ar[t] = Ap[(size_t)(b0 + lm + t * 16) * 1024 + kbase + lk];
        br[t] = Wp[(size_t)(o0 + lm + t * 16) * 1024 + kbase + lk];
    }
#pragma unroll
    for (int t = 0; t < 4; t++) {
        As[0][lk][lm + t * 16] = ar[t];
        Bs[0][lk][lm + t * 16] = br[t];
    }
    __syncthreads();

    float acc[4][4] = {};

#pragma unroll 1
    for (int kc = 0; kc < 8; kc++) {
        const int cur = kc & 1;
        if (kc < 7) {
            const int k0 = kbase + ((kc + 1) << 4);
#pragma unroll
            for (int t = 0; t < 4; t++) {
                ar[t] = Ap[(size_t)(b0 + lm + t * 16) * 1024 + k0 + lk];
                br[t] = Wp[(size_t)(o0 + lm + t * 16) * 1024 + k0 + lk];
            }
        }
#pragma unroll
        for (int kk = 0; kk < BK; kk++) {
            float4 a4 = *(const float4*)&As[cur][kk][ty << 2];  // warp broadcast
            float4 b4 = *(const float4*)&Bs[cur][kk][tx << 2];
            float av[4] = {a4.x, a4.y, a4.z, a4.w};
            float bv[4] = {b4.x, b4.y, b4.z, b4.w};
#pragma unroll
            for (int i = 0; i < 4; i++)
#pragma unroll
                for (int j = 0; j < 4; j++)
                    acc[i][j] = fmaf(av[i], bv[j], acc[i][j]);
        }
        if (kc < 7) {
            const int nxt = cur ^ 1;
#pragma unroll
            for (int t = 0; t < 4; t++) {
                As[nxt][lk][lm + t * 16] = ar[t];
                Bs[nxt][lk][lm + t * 16] = br[t];
            }
            __syncthreads();              // one barrier per chunk
        }
    }

    float* dst = &g_part[s][pp * 131072 + (size_t)(b0 + (ty << 2)) * 512 + o0 + (tx << 2)];
#pragma unroll
    for (int i = 0; i < 4; i++)
        *(float4*)(dst + (size_t)i * 512) =
            make_float4(acc[i][0], acc[i][1], acc[i][2], acc[i][3]);
}

__global__ void k_reduce(float* __restrict__ out) {
    int idx = blockIdx.x * 256 + threadIdx.x;   // < 262144
    // Fixed summation order -> deterministic
    float a = (g_part[0][idx] + g_part[1][idx]) + (g_part[2][idx] + g_part[3][idx]);
    float b = (g_part[4][idx] + g_part[5][idx]) + (g_part[6][idx] + g_part[7][idx]);
    out[idx] = a + b;
}

// ---------------------------------------------------------------------------

extern "C" void kernel_launch(void* const* d_in, const int* in_sizes, int n_in,
                              void* d_out, int out_size) {
    const float* x  = (const float*)d_in[0];
    const float* W  = (const float*)d_in[1];
    const float* B  = (const float*)d_in[2];
    const float* Wr = (const float*)d_in[3];
    const float* Wi = (const float*)d_in[4];
    float* out = (float*)d_out;

    cudaFuncSetAttribute(k_main, cudaFuncAttributeMaxDynamicSharedMemorySize, SMEM_MAIN);

    k_init<<<18 + 1024, 256>>>(W, B);
    k_main<<<296, 256, SMEM_MAIN>>>(x);
    k_gemm4<<<dim3(4, 8, 16), 256>>>(Wr, Wi);
    k_reduce<<<1024, 256>>>(out);
}

// round 9
// speedup vs baseline: 1.3862x; 1.3862x over previous
#include <cuda_runtime.h>

// ---------------------------------------------------------------------------
// ResonantComplexProjection
//   theta[b,n,i] = x[b,i] / (1+|W[n,i]|) + B[n,i]
//   idx = floor(theta * 4096/2pi) mod 4096   (LUT sin/cos, 4096 entries)
//   cos_sum[b,n] = sum_i cos_lut[idx];  sin_sum likewise
//   real = cos_sum @ Wr^T ; imag = sin_sum @ Wi^T
// Shapes: batch=256, in_f=512, n_neur=1024, out_f=512
// ---------------------------------------------------------------------------

#define LUT_HALF 4608                  // table covers k in [-4608, 4608)
#define LUT_N    (2 * LUT_HALF)        // 9216 entries (float2: sin, cos)
#define SMEM_MAIN (LUT_N * 8 + 2048)   // 72KB LUT + 2KB x tile = 75776 B (occ 2)

static __device__ float4 g_lut4[LUT_N / 2];    // 2 (sin,cos) entries per float4
static __device__ float4 g_rsbs[256 * 1024];   // [ipair][n] -> {rs0, rs1, bs0, bs1}
static __device__ float2 g_sums[4 * 262144];   // [iq][b][n] -> (sin_q, cos_q)
static __device__ float  g_A[2 * 262144];      // [p][b][k]: p0=cos, p1=sin
static __device__ float  g_part[8][262144];    // [ksplit][p*131072 + b*512 + o]

// ---------------------------------------------------------------------------
// Fused init: blocks [0,18) build the LUT; blocks [18,1042) build rs/bs.
// ---------------------------------------------------------------------------

__global__ void k_init(const float* __restrict__ W, const float* __restrict__ B) {
    const int bid = blockIdx.x;
    const int tid = threadIdx.x;
    if (bid < 18) {
        int t = bid * 256 + tid;                   // < 4608
        const float step = (float)(6.283185307179586476925287 / 4096.0);
        int k0 = 2 * t - LUT_HALF;
        int j0 = k0 & 4095;                        // floor-mod 4096 (matches Python %)
        int j1 = (k0 + 1) & 4095;
        float a0 = (float)j0 * step;
        float a1 = (float)j1 * step;
        float4 e;
        e.x = sinf(a0); e.y = cosf(a0);
        e.z = sinf(a1); e.w = cosf(a1);
        g_lut4[t] = e;
    } else {
        int e = (bid - 18) * 256 + tid;            // < 262144
        int n  = e & 1023;
        int ip = e >> 10;
        const float S = (float)(4096.0 / 6.283185307179586476925287);
        float2 w = ((const float2*)(W + n * 512))[ip];
        float2 b = ((const float2*)(B + n * 512))[ip];
        float4 v;
        v.x = S / (1.0f + fabsf(w.x));
        v.y = S / (1.0f + fabsf(w.y));
        v.z = S * b.x - 0.5f;                      // fold floor(v)=round(v-0.5) shift
        v.w = S * b.y - 0.5f;
        g_rsbs[e] = v;                             // e = ip*1024 + n
    }
}

// ---------------------------------------------------------------------------
// Packed f32x2 helpers
// ---------------------------------------------------------------------------

__device__ __forceinline__ unsigned long long fma2_(unsigned long long a,
                                                    unsigned long long b,
                                                    unsigned long long c) {
    unsigned long long d;
    asm("fma.rn.f32x2 %0, %1, %2, %3;" : "=l"(d) : "l"(a), "l"(b), "l"(c));
    return d;
}
__device__ __forceinline__ unsigned long long add2_(unsigned long long a,
                                                    unsigned long long b) {
    unsigned long long d;
    asm("add.rn.f32x2 %0, %1, %2;" : "=l"(d) : "l"(a), "l"(b));
    return d;
}
__device__ __forceinline__ unsigned long long lds64_(unsigned a) {
    unsigned long long v;
    asm("ld.shared.b64 %0, [%1];" : "=l"(v) : "r"(a));
    return v;
}

// ---------------------------------------------------------------------------
// k_main v3: 296 blocks (148 SMs x occ 2), STRIDED tile assignment.
// 1024 fine tiles = 4 n-tiles(256) x 64 batch-groups(4) x 4 i-quarters(64 ip).
// Strided t += 296 -> per-SM tile totals 7 vs avg 6.92 (1.2% imbalance) and
// cannot alias the 2-blocks-per-SM pairing (the R7 floor-division bug).
// Thread = 1 neuron x 4 batches: ONE LDG.128 {rs0,rs1,bs0,bs1} amortized over
// 4 batches -> 0.125 LDG-instr/element, same as the proven R6 rate.
// Inner math identical to proven path: magic-floor + extended LUT, e0-then-e1
// accumulation order per ip.
// ---------------------------------------------------------------------------

__global__ __launch_bounds__(256, 2) void k_main(const float* __restrict__ x) {
    extern __shared__ unsigned char smem[];
    float4* lut4 = (float4*)smem;
    unsigned long long* xs2 = (unsigned long long*)(smem + LUT_N * 8);  // [4 b][64 ip]

    const int tid = threadIdx.x;

#pragma unroll
    for (int t = 0; t < (LUT_N / 2) / 256; t++)        // stage 72KB LUT (18 iters)
        lut4[tid + t * 256] = g_lut4[tid + t * 256];

    const unsigned cbase =
        (unsigned)__cvta_generic_to_shared(smem) + (unsigned)(LUT_HALF * 8) - 0x5A000000u;
    const unsigned long long MAGIC2 = 0x4B4000004B400000ULL;

    const int lb  = tid >> 6;            // x-loader batch 0..3
    const int ipl = tid & 63;            // x-loader ipair 0..63

    for (int t = blockIdx.x; t < 1024; t += 296) {
        const int nt = t & 3;
        const int iq = (t >> 2) & 3;     // i-quarter (64 ipairs)
        const int bg = t >> 4;           // batch group of 4 (0..63)

        __syncthreads();                 // protect xs2 readers of previous tile
        xs2[tid] = ((const unsigned long long*)x)[((bg << 2) + lb) * 256 + (iq << 6) + ipl];
        __syncthreads();

        const int n = (nt << 8) + tid;
        const ulonglong2* rb =
            (const ulonglong2*)g_rsbs + (size_t)(iq << 6) * 1024 + n;

        unsigned long long acc[4];
#pragma unroll
        for (int b = 0; b < 4; b++) acc[b] = 0ULL;

#pragma unroll 2
        for (int ip = 0; ip < 64; ip++) {
            ulonglong2 rv = __ldg(rb + ip * 1024);    // {rs0,rs1},{bs0,bs1}
#pragma unroll
            for (int b = 0; b < 4; b++) {
                unsigned long long xp = xs2[(b << 6) + ip];   // bcast LDS.64
                unsigned long long w  = add2_(fma2_(xp, rv.x, rv.y), MAGIC2);
                unsigned qlo, qhi;
                asm("mov.b64 {%0, %1}, %2;" : "=r"(qlo), "=r"(qhi) : "l"(w));
                acc[b] = add2_(acc[b], lds64_(qlo * 8u + cbase));
                acc[b] = add2_(acc[b], lds64_(qhi * 8u + cbase));
            }
        }

        unsigned long long* sp =
            (unsigned long long*)g_sums + (size_t)iq * 262144 + (size_t)(bg << 2) * 1024 + n;
#pragma unroll
        for (int b = 0; b < 4; b++) sp[(size_t)b * 1024] = acc[b];
    }
}

// ---------------------------------------------------------------------------
// k_comb v2: sum the 4 i-quarter partials (fixed order) into cos/sin planes.
// ---------------------------------------------------------------------------

__global__ void k_comb() {
    int e = blockIdx.x * 256 + threadIdx.x;            // < 131072 float4s/plane
    const float4* p0 = (const float4*)g_sums;
    const float4* p1 = (const float4*)(g_sums + 262144);
    const float4* p2 = (const float4*)(g_sums + 2 * 262144);
    const float4* p3 = (const float4*)(g_sums + 3 * 262144);
    float4 a = p0[e], b = p1[e], c = p2[e], d = p3[e];
    float4 q;                                           // {s0,c0,s1,c1}
    q.x = (a.x + b.x) + (c.x + d.x);
    q.y = (a.y + b.y) + (c.y + d.y);
    q.z = (a.z + b.z) + (c.z + d.z);
    q.w = (a.w + b.w) + (c.w + d.w);
    ((float2*)g_A)[e]            = make_float2(q.y, q.w);   // cos plane
    ((float2*)(g_A + 262144))[e] = make_float2(q.x, q.z);   // sin plane
}

// ---------------------------------------------------------------------------
// k_gemm4 (UNCHANGED — proven): split-K GEMM, 64x64 tile, double-buffered,
// one sync per BK-chunk, `#pragma unroll 1` outer loop.
// grid (4,8,16) = 512 blocks: plane p (2) x K-split of 128 (8).
// ---------------------------------------------------------------------------

#define BK 16
#define LDP 68    // smem row stride in floats (float4-aligned)

__global__ __launch_bounds__(256, 3) void k_gemm4(const float* __restrict__ Wr,
                                                  const float* __restrict__ Wi) {
    __shared__ float As[2][BK][LDP];
    __shared__ float Bs[2][BK][LDP];

    const int tid = threadIdx.x;
    const int b0 = blockIdx.x << 6;
    const int o0 = blockIdx.y << 6;
    const int z  = blockIdx.z;
    const int pp = z >> 3;               // 0=real(cos), 1=imag(sin)
    const int s  = z & 7;                // K-split (128 each)

    const float* Ap = g_A + pp * 262144;
    const float* Wp = pp ? Wi : Wr;

    const int tx = tid & 15, ty = tid >> 4;
    const int lk = tid & 15;             // k within chunk
    const int lm = tid >> 4;             // base row 0..15 (4 strided rows)
    const int kbase = s << 7;

    float ar[4], br[4];
#pragma unroll
    for (int t = 0; t < 4; t++) {
        ar[t] = Ap[(size_t)(b0 + lm + t * 16) * 1024 + kbase + lk];
        br[t] = Wp[(size_t)(o0 + lm + t * 16) * 1024 + kbase + lk];
    }
#pragma unroll
    for (int t = 0; t < 4; t++) {
        As[0][lk][lm + t * 16] = ar[t];
        Bs[0][lk][lm + t * 16] = br[t];
    }
    __syncthreads();

    float acc[4][4] = {};

#pragma unroll 1
    for (int kc = 0; kc < 8; kc++) {
        const int cur = kc & 1;
        if (kc < 7) {
            const int k0 = kbase + ((kc + 1) << 4);
#pragma unroll
            for (int t = 0; t < 4; t++) {
                ar[t] = Ap[(size_t)(b0 + lm + t * 16) * 1024 + k0 + lk];
                br[t] = Wp[(size_t)(o0 + lm + t * 16) * 1024 + k0 + lk];
            }
        }
#pragma unroll
        for (int kk = 0; kk < BK; kk++) {
            float4 a4 = *(const float4*)&As[cur][kk][ty << 2];  // warp broadcast
            float4 b4 = *(const float4*)&Bs[cur][kk][tx << 2];
            float av[4] = {a4.x, a4.y, a4.z, a4.w};
            float bv[4] = {b4.x, b4.y, b4.z, b4.w};
#pragma unroll
            for (int i = 0; i < 4; i++)
#pragma unroll
                for (int j = 0; j < 4; j++)
                    acc[i][j] = fmaf(av[i], bv[j], acc[i][j]);
        }
        if (kc < 7) {
            const int nxt = cur ^ 1;
#pragma unroll
            for (int t = 0; t < 4; t++) {
                As[nxt][lk][lm + t * 16] = ar[t];
                Bs[nxt][lk][lm + t * 16] = br[t];
            }
            __syncthreads();              // one barrier per chunk
        }
    }

    float* dst = &g_part[s][pp * 131072 + (size_t)(b0 + (ty << 2)) * 512 + o0 + (tx << 2)];
#pragma unroll
    for (int i = 0; i < 4; i++)
        *(float4*)(dst + (size_t)i * 512) =
            make_float4(acc[i][0], acc[i][1], acc[i][2], acc[i][3]);
}

// ---------------------------------------------------------------------------
// k_reduce v2: float4-vectorized, MLP 8 per thread. Fixed order (same as R6).
// ---------------------------------------------------------------------------

__global__ void k_reduce(float* __restrict__ out) {
    int e = blockIdx.x * 256 + threadIdx.x;     // < 65536 float4s
    float4 p0 = ((const float4*)g_part[0])[e];
    float4 p1 = ((const float4*)g_part[1])[e];
    float4 p2 = ((const float4*)g_part[2])[e];
    float4 p3 = ((const float4*)g_part[3])[e];
    float4 p4 = ((const float4*)g_part[4])[e];
    float4 p5 = ((const float4*)g_part[5])[e];
    float4 p6 = ((const float4*)g_part[6])[e];
    float4 p7 = ((const float4*)g_part[7])[e];
    float4 r;
    r.x = ((p0.x + p1.x) + (p2.x + p3.x)) + ((p4.x + p5.x) + (p6.x + p7.x));
    r.y = ((p0.y + p1.y) + (p2.y + p3.y)) + ((p4.y + p5.y) + (p6.y + p7.y));
    r.z = ((p0.z + p1.z) + (p2.z + p3.z)) + ((p4.z + p5.z) + (p6.z + p7.z));
    r.w = ((p0.w + p1.w) + (p2.w + p3.w)) + ((p4.w + p5.w) + (p6.w + p7.w));
    ((float4*)out)[e] = r;
}

// ---------------------------------------------------------------------------

extern "C" void kernel_launch(void* const* d_in, const int* in_sizes, int n_in,
                              void* d_out, int out_size) {
    const float* x  = (const float*)d_in[0];
    const float* W  = (const float*)d_in[1];
    const float* B  = (const float*)d_in[2];
    const float* Wr = (const float*)d_in[3];
    const float* Wi = (const float*)d_in[4];
    float* out = (float*)d_out;

    cudaFuncSetAttribute(k_main, cudaFuncAttributeMaxDynamicSharedMemorySize, SMEM_MAIN);

    k_init<<<18 + 1024, 256>>>(W, B);
    k_main<<<296, 256, SMEM_MAIN>>>(x);
    k_comb<<<512, 256>>>();
    k_gemm4<<<dim3(4, 8, 16), 256>>>(Wr, Wi);
    k_reduce<<<256, 256>>>(out);
}

// round 10
// speedup vs baseline: 1.6688x; 1.2038x over previous
#include <cuda_runtime.h>

// ---------------------------------------------------------------------------
// ResonantComplexProjection
//   theta[b,n,i] = x[b,i] / (1+|W[n,i]|) + B[n,i]
//   idx = floor(theta * 4096/2pi) mod 4096   (LUT sin/cos, 4096 entries)
//   cos_sum[b,n] = sum_i cos_lut[idx];  sin_sum likewise
//   real = cos_sum @ Wr^T ; imag = sin_sum @ Wi^T
// Shapes: batch=256, in_f=512, n_neur=1024, out_f=512
// ---------------------------------------------------------------------------

#define LUT_HALF 4608                  // table covers k in [-4608, 4608)
#define LUT_N    (2 * LUT_HALF)        // 9216 packed entries {cos16|sin16}
#define SMEM_MAIN (LUT_N * 4 + 2048)   // 36KB LUT + 2KB x tile = 38912 B
#define LUT_SCALE 16384.0f             // int16 quantization scale (2^14)

static __device__ unsigned g_lut32[LUT_N];     // {(s16)(cos*16384)<<16 | (u16)(s16)(sin*16384)}
static __device__ float4 g_rsbs[256 * 1024];   // [ipair][n] -> {rs0, rs1, bs0, bs1}
static __device__ int2   g_sums[4 * 262144];   // [iq][b][n] -> (sin_acc, cos_acc) int32
static __device__ float  g_A[2 * 262144];      // [p][b][k]: p0=cos, p1=sin
static __device__ float  g_part[8][262144];    // [ksplit][p*131072 + b*512 + o]

// ---------------------------------------------------------------------------
// Fused init: blocks [0,18) build the int16 LUT; blocks [18,1042) build rs/bs.
// ---------------------------------------------------------------------------

__global__ void k_init(const float* __restrict__ W, const float* __restrict__ B) {
    const int bid = blockIdx.x;
    const int tid = threadIdx.x;
    if (bid < 18) {
        int t = bid * 256 + tid;                   // < 4608
        const float step = (float)(6.283185307179586476925287 / 4096.0);
        int k0 = 2 * t - LUT_HALF;
        int j0 = k0 & 4095;                        // floor-mod 4096 (matches Python %)
        int j1 = (k0 + 1) & 4095;
        float a0 = (float)j0 * step;
        float a1 = (float)j1 * step;
        int s0 = __float2int_rn(sinf(a0) * LUT_SCALE);   // |v| <= 16384, fits s16
        int c0 = __float2int_rn(cosf(a0) * LUT_SCALE);
        int s1 = __float2int_rn(sinf(a1) * LUT_SCALE);
        int c1 = __float2int_rn(cosf(a1) * LUT_SCALE);
        unsigned w0 = ((unsigned)(unsigned short)(short)c0 << 16) | (unsigned short)(short)s0;
        unsigned w1 = ((unsigned)(unsigned short)(short)c1 << 16) | (unsigned short)(short)s1;
        ((uint2*)g_lut32)[t] = make_uint2(w0, w1);
    } else {
        int e = (bid - 18) * 256 + tid;            // < 262144
        int n  = e & 1023;
        int ip = e >> 10;
        const float S = (float)(4096.0 / 6.283185307179586476925287);
        float2 w = ((const float2*)(W + n * 512))[ip];
        float2 b = ((const float2*)(B + n * 512))[ip];
        float4 v;
        v.x = S / (1.0f + fabsf(w.x));
        v.y = S / (1.0f + fabsf(w.y));
        v.z = S * b.x - 0.5f;                      // fold floor(v)=round(v-0.5) shift
        v.w = S * b.y - 0.5f;
        g_rsbs[e] = v;                             // e = ip*1024 + n
    }
}

// ---------------------------------------------------------------------------
// Packed helpers
// ---------------------------------------------------------------------------

__device__ __forceinline__ unsigned long long fma2_(unsigned long long a,
                                                    unsigned long long b,
                                                    unsigned long long c) {
    unsigned long long d;
    asm("fma.rn.f32x2 %0, %1, %2, %3;" : "=l"(d) : "l"(a), "l"(b), "l"(c));
    return d;
}
__device__ __forceinline__ unsigned long long add2_(unsigned long long a,
                                                    unsigned long long b) {
    unsigned long long d;
    asm("add.rn.f32x2 %0, %1, %2;" : "=l"(d) : "l"(a), "l"(b));
    return d;
}
__device__ __forceinline__ unsigned lds32_(unsigned a) {
    unsigned v;
    asm("ld.shared.b32 %0, [%1];" : "=r"(v) : "r"(a));
    return v;
}
// dp2a.lo: d = a.h0*b.b0 + a.h1*b.b1 + c  (16-bit halves of a, low 2 bytes of b)
__device__ __forceinline__ int dp2a_(unsigned a, unsigned b, int c) {
    int d;
    asm("dp2a.lo.s32.s32 %0, %1, %2, %3;" : "=r"(d) : "r"(a), "r"(b), "r"(c));
    return d;
}

// ---------------------------------------------------------------------------
// k_main v4: identical schedule to proven R8 version (296 blocks, strided
// 1024 fine tiles = 4 nt x 64 bg(4 batches) x 4 i-quarters; thread = 1 neuron
// x 4 batches, one LDG.128 rs|bs amortized over 4 batches).
// ONLY the LUT path changed: 4-byte packed int16 entries gathered via LDS.32
// (half the crossbar bank traffic) and accumulated EXACTLY in int32 via dp2a.
// Magic-floor addressing: addr = bits*4 + cbase, cbase folds the
// 0x4B400000*4 = 0x2D000000 (mod 2^32) wrap.
// ---------------------------------------------------------------------------

__global__ __launch_bounds__(256, 2) void k_main(const float* __restrict__ x) {
    extern __shared__ unsigned char smem[];
    uint4* lutv = (uint4*)smem;
    unsigned long long* xs2 = (unsigned long long*)(smem + LUT_N * 4);  // [4 b][64 ip]

    const int tid = threadIdx.x;

#pragma unroll
    for (int t = 0; t < (LUT_N / 4) / 256; t++)        // stage 36KB LUT (9 iters)
        lutv[tid + t * 256] = ((const uint4*)g_lut32)[tid + t * 256];

    const unsigned cbase =
        (unsigned)__cvta_generic_to_shared(smem) + (unsigned)(LUT_HALF * 4) - 0x2D000000u;
    const unsigned long long MAGIC2 = 0x4B4000004B400000ULL;
    const unsigned SEL_S = 0x00000001u;   // dp2a: take low half (sin)
    const unsigned SEL_C = 0x00000100u;   // dp2a: take high half (cos)

    const int lb  = tid >> 6;            // x-loader batch 0..3
    const int ipl = tid & 63;            // x-loader ipair 0..63

    for (int t = blockIdx.x; t < 1024; t += 296) {
        const int nt = t & 3;
        const int iq = (t >> 2) & 3;     // i-quarter (64 ipairs)
        const int bg = t >> 4;           // batch group of 4 (0..63)

        __syncthreads();                 // protect xs2 readers of previous tile
        xs2[tid] = ((const unsigned long long*)x)[((bg << 2) + lb) * 256 + (iq << 6) + ipl];
        __syncthreads();

        const int n = (nt << 8) + tid;
        const ulonglong2* rb =
            (const ulonglong2*)g_rsbs + (size_t)(iq << 6) * 1024 + n;

        int accS[4], accC[4];
#pragma unroll
        for (int b = 0; b < 4; b++) { accS[b] = 0; accC[b] = 0; }

#pragma unroll 2
        for (int ip = 0; ip < 64; ip++) {
            ulonglong2 rv = __ldg(rb + ip * 1024);    // {rs0,rs1},{bs0,bs1}
#pragma unroll
            for (int b = 0; b < 4; b++) {
                unsigned long long xp = xs2[(b << 6) + ip];   // bcast LDS.64
                unsigned long long w  = add2_(fma2_(xp, rv.x, rv.y), MAGIC2);
                unsigned qlo, qhi;
                asm("mov.b64 {%0, %1}, %2;" : "=r"(qlo), "=r"(qhi) : "l"(w));
                unsigned e0 = lds32_(qlo * 4u + cbase);       // {cos16|sin16}
                unsigned e1 = lds32_(qhi * 4u + cbase);
                accS[b] = dp2a_(e0, SEL_S, accS[b]);
                accC[b] = dp2a_(e0, SEL_C, accC[b]);
                accS[b] = dp2a_(e1, SEL_S, accS[b]);
                accC[b] = dp2a_(e1, SEL_C, accC[b]);
            }
        }

        int2* sp = g_sums + (size_t)iq * 262144 + (size_t)(bg << 2) * 1024 + n;
#pragma unroll
        for (int b = 0; b < 4; b++) sp[(size_t)b * 1024] = make_int2(accS[b], accC[b]);
    }
}

// ---------------------------------------------------------------------------
// k_comb v3: integer-sum the 4 i-quarter partials (EXACT), then one scale to
// float into the cos/sin planes.
// ---------------------------------------------------------------------------

__global__ void k_comb() {
    int e = blockIdx.x * 256 + threadIdx.x;            // < 131072 int4s/quarter
    const int4* p0 = (const int4*)g_sums;              // {s0,c0,s1,c1}
    const int4* p1 = (const int4*)(g_sums + 262144);
    const int4* p2 = (const int4*)(g_sums + 2 * 262144);
    const int4* p3 = (const int4*)(g_sums + 3 * 262144);
    int4 a = p0[e], b = p1[e], c = p2[e], d = p3[e];
    int s0 = (a.x + b.x) + (c.x + d.x);
    int c0 = (a.y + b.y) + (c.y + d.y);
    int s1 = (a.z + b.z) + (c.z + d.z);
    int c1 = (a.w + b.w) + (c.w + d.w);
    const float SC = 1.0f / LUT_SCALE;
    ((float2*)g_A)[e]            = make_float2((float)c0 * SC, (float)c1 * SC); // cos
    ((float2*)(g_A + 262144))[e] = make_float2((float)s0 * SC, (float)s1 * SC); // sin
}

// ---------------------------------------------------------------------------
// k_gemm4 (UNCHANGED — proven): split-K GEMM, 64x64 tile, double-buffered,
// one sync per BK-chunk, `#pragma unroll 1` outer loop.
// grid (4,8,16) = 512 blocks: plane p (2) x K-split of 128 (8).
// ---------------------------------------------------------------------------

#define BK 16
#define LDP 68    // smem row stride in floats (float4-aligned)

__global__ __launch_bounds__(256, 3) void k_gemm4(const float* __restrict__ Wr,
                                                  const float* __restrict__ Wi) {
    __shared__ float As[2][BK][LDP];
    __shared__ float Bs[2][BK][LDP];

    const int tid = threadIdx.x;
    const int b0 = blockIdx.x << 6;
    const int o0 = blockIdx.y << 6;
    const int z  = blockIdx.z;
    const int pp = z >> 3;               // 0=real(cos), 1=imag(sin)
    const int s  = z & 7;                // K-split (128 each)

    const float* Ap = g_A + pp * 262144;
    const float* Wp = pp ? Wi : Wr;

    const int tx = tid & 15, ty = tid >> 4;
    const int lk = tid & 15;             // k within chunk
    const int lm = tid >> 4;             // base row 0..15 (4 strided rows)
    const int kbase = s << 7;

    float ar[4], br[4];
#pragma unroll
    for (int t = 0; t < 4; t++) {
        ar[t] = Ap[(size_t)(b0 + lm + t * 16) * 1024 + kbase + lk];
        br[t] = Wp[(size_t)(o0 + lm + t * 16) * 1024 + kbase + lk];
    }
#pragma unroll
    for (int t = 0; t < 4; t++) {
        As[0][lk][lm + t * 16] = ar[t];
        Bs[0][lk][lm + t * 16] = br[t];
    }
    __syncthreads();

    float acc[4][4] = {};

#pragma unroll 1
    for (int kc = 0; kc < 8; kc++) {
        const int cur = kc & 1;
        if (kc < 7) {
            const int k0 = kbase + ((kc + 1) << 4);
#pragma unroll
            for (int t = 0; t < 4; t++) {
                ar[t] = Ap[(size_t)(b0 + lm + t * 16) * 1024 + k0 + lk];
                br[t] = Wp[(size_t)(o0 + lm + t * 16) * 1024 + k0 + lk];
            }
        }
#pragma unroll
        for (int kk = 0; kk < BK; kk++) {
            float4 a4 = *(const float4*)&As[cur][kk][ty << 2];  // warp broadcast
            float4 b4 = *(const float4*)&Bs[cur][kk][tx << 2];
            float av[4] = {a4.x, a4.y, a4.z, a4.w};
            float bv[4] = {b4.x, b4.y, b4.z, b4.w};
#pragma unroll
            for (int i = 0; i < 4; i++)
#pragma unroll
                for (int j = 0; j < 4; j++)
                    acc[i][j] = fmaf(av[i], bv[j], acc[i][j]);
        }
        if (kc < 7) {
            const int nxt = cur ^ 1;
#pragma unroll
            for (int t = 0; t < 4; t++) {
                As[nxt][lk][lm + t * 16] = ar[t];
                Bs[nxt][lk][lm + t * 16] = br[t];
            }
            __syncthreads();              // one barrier per chunk
        }
    }

    float* dst = &g_part[s][pp * 131072 + (size_t)(b0 + (ty << 2)) * 512 + o0 + (tx << 2)];
#pragma unroll
    for (int i = 0; i < 4; i++)
        *(float4*)(dst + (size_t)i * 512) =
            make_float4(acc[i][0], acc[i][1], acc[i][2], acc[i][3]);
}

// ---------------------------------------------------------------------------
// k_reduce (UNCHANGED — proven): float4-vectorized, fixed order.
// ---------------------------------------------------------------------------

__global__ void k_reduce(float* __restrict__ out) {
    int e = blockIdx.x * 256 + threadIdx.x;     // < 65536 float4s
    float4 p0 = ((const float4*)g_part[0])[e];
    float4 p1 = ((const float4*)g_part[1])[e];
    float4 p2 = ((const float4*)g_part[2])[e];
    float4 p3 = ((const float4*)g_part[3])[e];
    float4 p4 = ((const float4*)g_part[4])[e];
    float4 p5 = ((const float4*)g_part[5])[e];
    float4 p6 = ((const float4*)g_part[6])[e];
    float4 p7 = ((const float4*)g_part[7])[e];
    float4 r;
    r.x = ((p0.x + p1.x) + (p2.x + p3.x)) + ((p4.x + p5.x) + (p6.x + p7.x));
    r.y = ((p0.y + p1.y) + (p2.y + p3.y)) + ((p4.y + p5.y) + (p6.y + p7.y));
    r.z = ((p0.z + p1.z) + (p2.z + p3.z)) + ((p4.z + p5.z) + (p6.z + p7.z));
    r.w = ((p0.w + p1.w) + (p2.w + p3.w)) + ((p4.w + p5.w) + (p6.w + p7.w));
    ((float4*)out)[e] = r;
}

// ---------------------------------------------------------------------------

extern "C" void kernel_launch(void* const* d_in, const int* in_sizes, int n_in,
                              void* d_out, int out_size) {
    const float* x  = (const float*)d_in[0];
    const float* W  = (const float*)d_in[1];
    const float* B  = (const float*)d_in[2];
    const float* Wr = (const float*)d_in[3];
    const float* Wi = (const float*)d_in[4];
    float* out = (float*)d_out;

    cudaFuncSetAttribute(k_main, cudaFuncAttributeMaxDynamicSharedMemorySize, SMEM_MAIN);

    k_init<<<18 + 1024, 256>>>(W, B);
    k_main<<<296, 256, SMEM_MAIN>>>(x);
    k_comb<<<512, 256>>>();
    k_gemm4<<<dim3(4, 8, 16), 256>>>(Wr, Wi);
    k_reduce<<<256, 256>>>(out);
}